// round 2
// baseline (speedup 1.0000x reference)
#include <cuda_runtime.h>
#include <math.h>

#define MM    16
#define TT    512
#define DD    512
#define HH    512
#define QKN   256
#define KACT  4
#define NG    148
#define TPB   256
#define NWARP 8
#define GWARPS (NG*NWARP)
#define NTHREADS (NG*TPB)

// ---------------- persistent scratch (device globals; no allocs allowed) ----------------
__device__ __align__(16) float g_h  [MM*HH];
__device__ __align__(16) float g_c  [MM*HH];
__device__ __align__(16) float g_q  [MM*QKN];
__device__ __align__(16) float g_kx [MM*QKN];
__device__ __align__(16) float g_sel[MM*DD];
__device__ __align__(16) float g_th [MM*HH];
__device__ __align__(16) float g_q2 [MM*HH];
__device__ __align__(16) float g_k2 [MM*HH];
__device__ __align__(16) float g_v2 [MM*HH];
__device__ unsigned g_barCnt;   // zero-initialized; barrier resets it to 0 each use
__device__ unsigned g_barGen;   // monotonic generation; each launch reads start value

// ---------------- helpers ----------------
__device__ __forceinline__ float warp_reduce(float s) {
#pragma unroll
  for (int o = 16; o; o >>= 1) s += __shfl_xor_sync(0xffffffffu, s, o);
  return s;
}

__device__ __forceinline__ float sigf(float x) { return 1.f / (1.f + expf(-x)); }

// warp dot of length N4*128 floats. ACG/BCG: read via L2 (.cg) for mutable scratch.
template<int N4, bool ACG, bool BCG>
__device__ __forceinline__ float wdot(const float* __restrict__ A,
                                      const float* __restrict__ B, int lane) {
  const float4* a4 = (const float4*)A;
  const float4* b4 = (const float4*)B;
  float s = 0.f;
#pragma unroll
  for (int k = 0; k < N4; k++) {
    int idx = lane + 32 * k;
    float4 a = ACG ? __ldcg(a4 + idx) : __ldg(a4 + idx);
    float4 b = BCG ? __ldcg(b4 + idx) : __ldg(b4 + idx);
    s = fmaf(a.x, b.x, s); s = fmaf(a.y, b.y, s);
    s = fmaf(a.z, b.z, s); s = fmaf(a.w, b.w, s);
  }
  return warp_reduce(s);
}

// shared-memory dot of 512 floats
__device__ __forceinline__ float sdot512(const float* a, const float* b, int lane) {
  float s = 0.f;
#pragma unroll
  for (int k = 0; k < 4; k++) {
    float4 av = ((const float4*)a)[lane + 32 * k];
    float4 bv = ((const float4*)b)[lane + 32 * k];
    s = fmaf(av.x, bv.x, s); s = fmaf(av.y, bv.y, s);
    s = fmaf(av.z, bv.z, s); s = fmaf(av.w, bv.w, s);
  }
  return warp_reduce(s);
}

// transposed GEMV quarter: out[o] = sum_h vec[h] * W[h*HH + o], o in [qt*128, qt*128+128)
// W is a read-only weight [HH x HH] row-major; vec is mutable scratch (ldcg).
__device__ __forceinline__ void tgemv_q(const float* __restrict__ W,
                                        const float* __restrict__ vec,
                                        float* __restrict__ outp, int qt, int lane) {
  const int o0 = qt * 128;
  float4 acc = make_float4(0.f, 0.f, 0.f, 0.f);
  const float4* vp = (const float4*)vec;
#pragma unroll 2
  for (int h4 = 0; h4 < HH / 4; h4++) {
    float4 tv = __ldcg(vp + h4);                  // broadcast across warp
    const float* base = W + (size_t)(h4 * 4) * HH + o0;
    float4 w0 = __ldg((const float4*)(base) + lane);
    float4 w1 = __ldg((const float4*)(base + HH) + lane);
    float4 w2 = __ldg((const float4*)(base + 2 * HH) + lane);
    float4 w3 = __ldg((const float4*)(base + 3 * HH) + lane);
    acc.x = fmaf(tv.x, w0.x, fmaf(tv.y, w1.x, fmaf(tv.z, w2.x, fmaf(tv.w, w3.x, acc.x))));
    acc.y = fmaf(tv.x, w0.y, fmaf(tv.y, w1.y, fmaf(tv.z, w2.y, fmaf(tv.w, w3.y, acc.y))));
    acc.z = fmaf(tv.x, w0.z, fmaf(tv.y, w1.z, fmaf(tv.z, w2.z, fmaf(tv.w, w3.z, acc.z))));
    acc.w = fmaf(tv.x, w0.w, fmaf(tv.y, w1.w, fmaf(tv.z, w2.w, fmaf(tv.w, w3.w, acc.w))));
  }
  __stcg((float4*)(outp + o0) + lane, acc);
}

// software grid barrier (all NG CTAs co-resident: grid == 148 <= SM count, 1 CTA/SM)
__device__ __forceinline__ void gbar(unsigned& lgen) {
  __syncthreads();
  if (threadIdx.x == 0) {
    __threadfence();
    if (atomicAdd(&g_barCnt, 1u) == (unsigned)(NG - 1)) {
      g_barCnt = 0u;
      __threadfence();
      atomicAdd(&g_barGen, 1u);
    } else {
      while (*((volatile unsigned*)&g_barGen) == lgen) { }
    }
    __threadfence();
  }
  lgen++;
  __syncthreads();
}

// ---------------- main persistent kernel ----------------
__global__ void __launch_bounds__(TPB, 1)
rim_kernel(const float* __restrict__ inputs,
           const float* __restrict__ Wq,  const float* __restrict__ bq,
           const float* __restrict__ Wk,  const float* __restrict__ bk,
           const float* __restrict__ Wv,  const float* __restrict__ bv,
           const float* __restrict__ W_ih, const float* __restrict__ b_ih,
           const float* __restrict__ W_hh, const float* __restrict__ b_hh,
           const float* __restrict__ Wqg, const float* __restrict__ Wkg,
           const float* __restrict__ Wvg,
           float* __restrict__ out, int outTotal) {
  const int lane = threadIdx.x & 31;
  const int warp = threadIdx.x >> 5;
  const int gw   = blockIdx.x * NWARP + warp;   // global warp id
  const int gt   = blockIdx.x * TPB + threadIdx.x;

  __shared__ float s_att0[MM], s_att1[MM];
  __shared__ int   s_act[KACT], s_inact[MM - KACT], s_slot[MM];
  __shared__ float s_s[KACT * MM], s_w[KACT * MM];
  __shared__ __align__(16) float s_q2b[KACT * HH];  // 8 KB
  __shared__ __align__(16) float s_k2b[MM * HH];    // 32 KB

  unsigned lgen = *((volatile unsigned*)&g_barGen);  // launch-stable start generation

  // init state h0 = c0 = 0
  for (int e = gt; e < MM * HH; e += NTHREADS) { g_h[e] = 0.f; g_c[e] = 0.f; }
  gbar(lgen);

  for (int t = 0; t < TT; ++t) {
    const float* xrowbase = inputs + (size_t)t * DD;   // + m*TT*DD per module

    // ---- Phase 1: q = Wq@h + bq ; key_x = Wk@x_t + bk  (all modules) ----
    for (int task = gw; task < MM * QKN; task += GWARPS) {
      int m = task >> 8, i = task & 255;
      const float* xm = inputs + ((size_t)m * TT + t) * DD;
      float qv = wdot<4, false, true >(Wq + (size_t)(m * QKN + i) * HH, g_h + m * HH, lane);
      float kv = wdot<4, false, false>(Wk + (size_t)(m * QKN + i) * DD, xm, lane);
      if (lane == 0) { g_q[task] = qv + bq[task]; g_kx[task] = kv + bk[task]; }
    }
    gbar(lgen);

    // ---- Phase 2 (redundant per CTA, deterministic): logits, softmax(2), top-k ----
    for (int m = warp; m < MM; m += NWARP) {
      float l0 = wdot<2, true, false>(g_q + m * QKN, bk + m * QKN, lane);
      float l1 = wdot<2, true, true >(g_q + m * QKN, g_kx + m * QKN, lane);
      if (lane == 0) {
        const float scale = 1.f / 16.f;   // 1/sqrt(QK=256)
        l0 *= scale; l1 *= scale;
        float mx = fmaxf(l0, l1);
        float e0 = expf(l0 - mx), e1 = expf(l1 - mx);
        float inv = 1.f / (e0 + e1);
        s_att0[m] = e0 * inv; s_att1[m] = e1 * inv;
      }
    }
    __syncthreads();
    if (threadIdx.x == 0) {
      // top_k(-att0): K smallest att0, ties -> lowest index (strict '<' keeps first)
      bool used[MM];
#pragma unroll
      for (int j = 0; j < MM; j++) used[j] = false;
      for (int k = 0; k < KACT; k++) {
        int best = 0; float bvv = 3.402823466e38f;
        for (int j = 0; j < MM; j++)
          if (!used[j] && s_att0[j] < bvv) { bvv = s_att0[j]; best = j; }
        used[best] = true; s_act[k] = best;
        if (blockIdx.x == 0 && outTotal >= TT * MM * HH + TT * KACT)
          out[(size_t)TT * MM * HH + (size_t)t * KACT + k] = (float)best;
      }
      for (int j = 0; j < MM; j++) s_slot[j] = -1;
      for (int k = 0; k < KACT; k++) s_slot[s_act[k]] = k;
      int ii = 0;
      for (int j = 0; j < MM; j++) if (s_slot[j] < 0) s_inact[ii++] = j;
    }
    __syncthreads();

    // ---- Phase 3: inactive k2/v2 (from old h), active val1+sel ----
    {
      const int NHEAVY = (MM - KACT) * 2 * 4;  // 96 quarter-tile tasks
      for (int task = gw; task < NHEAVY + KACT * DD; task += GWARPS) {
        if (task < NHEAVY) {
          int im = task % (MM - KACT);
          int rest = task / (MM - KACT);
          int mat = rest >> 2, qt = rest & 3;
          int m = s_inact[im];
          const float* W = (mat ? Wvg : Wkg) + (size_t)m * HH * HH;
          float* op = (mat ? g_v2 : g_k2) + m * HH;
          tgemv_q(W, g_h + m * HH, op, qt, lane);   // temp_h == h for inactive
        } else {
          int lt = task - NHEAVY;
          int a = lt >> 9, r = lt & 511;
          int m = s_act[a];
          const float* xm = inputs + ((size_t)m * TT + t) * DD;
          float bvv = bv[m * DD + r];
          float v1 = wdot<4, false, false>(Wv + (size_t)(m * DD + r) * DD, xm, lane) + bvv;
          if (lane == 0)
            g_sel[m * DD + r] = s_att0[m] * bvv + s_att1[m] * v1;
        }
      }
    }
    gbar(lgen);

    // ---- Phase 4: gates + LSTM (active only, fused), zero c for inactive ----
    for (int task = gw; task < KACT * HH; task += GWARPS) {
      int a = task >> 9, j = task & 511;
      int m = s_act[a];
      const float* Wi = W_ih + (size_t)m * 4 * HH * DD;
      const float* Wh = W_hh + (size_t)m * 4 * HH * HH;
      float gv[4];
#pragma unroll
      for (int gq = 0; gq < 4; gq++) {
        int row = gq * HH + j;
        float s1 = wdot<4, false, true>(Wi + (size_t)row * DD, g_sel + m * DD, lane);
        float s2 = wdot<4, false, true>(Wh + (size_t)row * HH, g_h + m * HH, lane);
        gv[gq] = s1 + s2 + b_ih[m * 4 * HH + row] + b_hh[m * 4 * HH + row];
      }
      if (lane == 0) {
        float iv = gv[0], fv = gv[1], gg = gv[2], ov = gv[3];
        float co = __ldcg(&g_c[m * HH + j]);
        float cn = sigf(fv) * co + sigf(iv) * tanhf(gg);
        float hn = sigf(ov) * tanhf(cn);
        __stcg(&g_c[m * HH + j], cn);   // new_c = c_new (active)
        __stcg(&g_th[m * HH + j], hn);  // temp_h = h_new (active)
      }
    }
    for (int e = gt; e < (MM - KACT) * HH; e += NTHREADS) {
      int m = s_inact[e >> 9];
      __stcg(&g_c[m * HH + (e & 511)], 0.f);  // new_c = 0 for inactive
    }
    gbar(lgen);

    // ---- Phase 5: q2/k2/v2 for active modules (from temp_h) ----
    for (int task = gw; task < KACT * 12; task += GWARPS) {
      int a = task / 12, rest = task % 12;
      int mat = rest >> 2, qt = rest & 3;
      int m = s_act[a];
      const float* W = (mat == 0 ? Wqg : (mat == 1 ? Wkg : Wvg)) + (size_t)m * HH * HH;
      float* op = (mat == 0 ? g_q2 : (mat == 1 ? g_k2 : g_v2)) + m * HH;
      tgemv_q(W, g_th + m * HH, op, qt, lane);
    }
    gbar(lgen);

    // ---- Phase 6: att2 (redundant per CTA from smem), inter, new_h, output ----
    for (int idx = threadIdx.x; idx < KACT * HH; idx += TPB)
      s_q2b[idx] = __ldcg(&g_q2[s_act[idx >> 9] * HH + (idx & 511)]);
    for (int idx = threadIdx.x; idx < MM * HH; idx += TPB)
      s_k2b[idx] = __ldcg(&g_k2[idx]);
    __syncthreads();
    for (int d6 = warp; d6 < KACT * MM; d6 += NWARP) {
      int a = d6 >> 4, j = d6 & 15;
      float s = sdot512(s_q2b + a * HH, s_k2b + j * HH, lane);
      if (lane == 0) s_s[d6] = s;
    }
    __syncthreads();
    if (threadIdx.x < KACT) {
      int a = threadIdx.x;
      float mx = -3.402823466e38f;
#pragma unroll
      for (int j = 0; j < MM; j++) mx = fmaxf(mx, s_s[a * MM + j]);
      float ev[MM]; float sum = 0.f;
#pragma unroll
      for (int j = 0; j < MM; j++) { ev[j] = expf(s_s[a * MM + j] - mx); sum += ev[j]; }
      float inv = 1.f / sum;
#pragma unroll
      for (int j = 0; j < MM; j++) s_w[a * MM + j] = ev[j] * inv;
    }
    __syncthreads();
    for (int e = gt; e < MM * HH; e += NTHREADS) {
      int m = e >> 9, d = e & 511;
      int a = s_slot[m];
      float val;
      if (a >= 0) {   // active: new_h = att2@v2 + temp_h
        float acc = 0.f;
#pragma unroll
        for (int j = 0; j < MM; j++)
          acc = fmaf(s_w[a * MM + j], __ldcg(&g_v2[j * HH + d]), acc);
        val = acc + __ldcg(&g_th[e]);
        __stcg(&g_h[e], val);
      } else {        // inactive: new_h = h
        val = __ldcg(&g_h[e]);
      }
      out[(size_t)t * MM * HH + e] = val;
    }
    gbar(lgen);
  }
}

// ---------------- launch ----------------
extern "C" void kernel_launch(void* const* d_in, const int* in_sizes, int n_in,
                              void* d_out, int out_size) {
  (void)in_sizes; (void)n_in;
  rim_kernel<<<NG, TPB>>>(
      (const float*)d_in[0],  (const float*)d_in[1],  (const float*)d_in[2],
      (const float*)d_in[3],  (const float*)d_in[4],  (const float*)d_in[5],
      (const float*)d_in[6],  (const float*)d_in[7],  (const float*)d_in[8],
      (const float*)d_in[9],  (const float*)d_in[10], (const float*)d_in[11],
      (const float*)d_in[12], (const float*)d_in[13],
      (float*)d_out, out_size);
}

// round 3
// speedup vs baseline: 3.0103x; 3.0103x over previous
#include <cuda_runtime.h>
#include <math.h>

#define MM    16
#define TT    512
#define DD    512
#define HH    512
#define QKN   256
#define KACT  4
#define NG    148
#define TPB   512
#define NWARP (TPB/32)              // 16
#define GWARPS (NG*NWARP)           // 2368
#define NTHREADS (NG*TPB)           // 75776
#define NCH   16                    // h-chunks per transposed GEMV
#define CHROWS (HH/NCH)             // 32

// ---------------- persistent scratch (device globals; no allocs allowed) ----------------
__device__ __align__(16) float g_h  [MM*HH];
__device__ __align__(16) float g_c  [MM*HH];
__device__ __align__(16) float g_q  [MM*QKN];
__device__ __align__(16) float g_kx [MM*QKN];
__device__ __align__(16) float g_sel[MM*DD];
__device__ __align__(16) float g_th [MM*HH];
__device__ __align__(16) float g_q2 [MM*HH];
__device__ __align__(16) float g_k2 [MM*HH];
__device__ __align__(16) float g_v2 [MM*HH];
__device__ __align__(16) float g_part[3][MM][NCH][HH];   // mat 0=q2,1=k2,2=v2 partials
__device__ unsigned g_barCnt;
__device__ unsigned g_barGen;

// ---------------- helpers ----------------
__device__ __forceinline__ float warp_reduce(float s) {
#pragma unroll
  for (int o = 16; o; o >>= 1) s += __shfl_xor_sync(0xffffffffu, s, o);
  return s;
}

__device__ __forceinline__ float sigf(float x) { return 1.f / (1.f + expf(-x)); }

// warp dot of length N4*128 floats. ACG/BCG: read via L2 (.cg) for mutable scratch.
template<int N4, bool ACG, bool BCG>
__device__ __forceinline__ float wdot(const float* __restrict__ A,
                                      const float* __restrict__ B, int lane) {
  const float4* a4 = (const float4*)A;
  const float4* b4 = (const float4*)B;
  float s = 0.f;
#pragma unroll
  for (int k = 0; k < N4; k++) {
    int idx = lane + 32 * k;
    float4 a = ACG ? __ldcg(a4 + idx) : __ldg(a4 + idx);
    float4 b = BCG ? __ldcg(b4 + idx) : __ldg(b4 + idx);
    s = fmaf(a.x, b.x, s); s = fmaf(a.y, b.y, s);
    s = fmaf(a.z, b.z, s); s = fmaf(a.w, b.w, s);
  }
  return warp_reduce(s);
}

// shared-memory dot of 512 floats
__device__ __forceinline__ float sdot512(const float* a, const float* b, int lane) {
  float s = 0.f;
#pragma unroll
  for (int k = 0; k < 4; k++) {
    float4 av = ((const float4*)a)[lane + 32 * k];
    float4 bv = ((const float4*)b)[lane + 32 * k];
    s = fmaf(av.x, bv.x, s); s = fmaf(av.y, bv.y, s);
    s = fmaf(av.z, bv.z, s); s = fmaf(av.w, bv.w, s);
  }
  return warp_reduce(s);
}

// Chunked transposed GEMV partial:
//   outp[o] = sum_{h in [ch*CHROWS, (ch+1)*CHROWS)} vec[h] * W[h*HH + o]
//   for o in [qt*128, qt*128+128). One warp, fully unrolled -> 32 weight loads in flight.
__device__ __forceinline__ void tgemv_part(const float* __restrict__ W,
                                           const float* __restrict__ vec,
                                           float* __restrict__ outp,
                                           int qt, int ch, int lane) {
  const int o0 = qt * 128;
  const int h0 = ch * CHROWS;
  float4 acc = make_float4(0.f, 0.f, 0.f, 0.f);
  const float4* vp = (const float4*)(vec + h0);
#pragma unroll
  for (int i = 0; i < CHROWS / 4; i++) {           // 8 iterations
    float4 tv = __ldcg(vp + i);
    const float* base = W + (size_t)(h0 + i * 4) * HH + o0;
    float4 w0 = __ldg((const float4*)(base) + lane);
    float4 w1 = __ldg((const float4*)(base + HH) + lane);
    float4 w2 = __ldg((const float4*)(base + 2 * HH) + lane);
    float4 w3 = __ldg((const float4*)(base + 3 * HH) + lane);
    acc.x = fmaf(tv.x, w0.x, fmaf(tv.y, w1.x, fmaf(tv.z, w2.x, fmaf(tv.w, w3.x, acc.x))));
    acc.y = fmaf(tv.x, w0.y, fmaf(tv.y, w1.y, fmaf(tv.z, w2.y, fmaf(tv.w, w3.y, acc.y))));
    acc.z = fmaf(tv.x, w0.z, fmaf(tv.y, w1.z, fmaf(tv.z, w2.z, fmaf(tv.w, w3.z, acc.z))));
    acc.w = fmaf(tv.x, w0.w, fmaf(tv.y, w1.w, fmaf(tv.z, w2.w, fmaf(tv.w, w3.w, acc.w))));
  }
  __stcg((float4*)(outp + o0) + lane, acc);
}

// software grid barrier (all NG CTAs co-resident: grid == 148 <= SM count)
__device__ __forceinline__ void gbar(unsigned& lgen) {
  __syncthreads();
  if (threadIdx.x == 0) {
    __threadfence();
    if (atomicAdd(&g_barCnt, 1u) == (unsigned)(NG - 1)) {
      g_barCnt = 0u;
      __threadfence();
      atomicAdd(&g_barGen, 1u);
    } else {
      while (*((volatile unsigned*)&g_barGen) == lgen) { }
    }
    __threadfence();
  }
  lgen++;
  __syncthreads();
}

// ---------------- main persistent kernel ----------------
__global__ void __launch_bounds__(TPB, 1)
rim_kernel(const float* __restrict__ inputs,
           const float* __restrict__ Wq,  const float* __restrict__ bq,
           const float* __restrict__ Wk,  const float* __restrict__ bk,
           const float* __restrict__ Wv,  const float* __restrict__ bv,
           const float* __restrict__ W_ih, const float* __restrict__ b_ih,
           const float* __restrict__ W_hh, const float* __restrict__ b_hh,
           const float* __restrict__ Wqg, const float* __restrict__ Wkg,
           const float* __restrict__ Wvg,
           float* __restrict__ out, int outTotal) {
  const int lane = threadIdx.x & 31;
  const int warp = threadIdx.x >> 5;
  const int gw   = blockIdx.x * NWARP + warp;
  const int gt   = blockIdx.x * TPB + threadIdx.x;

  __shared__ float s_att0[MM], s_att1[MM];
  __shared__ int   s_act[KACT], s_inact[MM - KACT], s_slot[MM];
  __shared__ float s_s[KACT * MM], s_w[KACT * MM];
  __shared__ __align__(16) float s_q2b[KACT * HH];  // 8 KB
  __shared__ __align__(16) float s_k2b[MM * HH];    // 32 KB

  unsigned lgen = *((volatile unsigned*)&g_barGen);

  for (int e = gt; e < MM * HH; e += NTHREADS) { g_h[e] = 0.f; g_c[e] = 0.f; }
  gbar(lgen);

  for (int t = 0; t < TT; ++t) {

    // ---- P1: q = Wq@h + bq ; key_x = Wk@x_t + bk (all modules; 4096 warp-tasks) ----
    for (int task = gw; task < MM * QKN; task += GWARPS) {
      int m = task >> 8;
      const float* xm = inputs + ((size_t)m * TT + t) * DD;
      float qv = wdot<4, false, true >(Wq + (size_t)task * HH, g_h + m * HH, lane);
      float kv = wdot<4, false, false>(Wk + (size_t)task * DD, xm, lane);
      if (lane == 0) { g_q[task] = qv + __ldg(bq + task); g_kx[task] = kv + __ldg(bk + task); }
    }
    gbar(lgen);

    // ---- P2: softmax(2)+topk (redundant per CTA) ; then val1/sel + inactive k2/v2 partials ----
    if (warp < MM) {
      int m = warp;
      float l0 = wdot<2, true, false>(g_q + m * QKN, bk + m * QKN, lane);
      float l1 = wdot<2, true, true >(g_q + m * QKN, g_kx + m * QKN, lane);
      if (lane == 0) {
        const float scale = 1.f / 16.f;           // 1/sqrt(QK=256)
        l0 *= scale; l1 *= scale;
        float mx = fmaxf(l0, l1);
        float e0 = expf(l0 - mx), e1 = expf(l1 - mx);
        float inv = 1.f / (e0 + e1);
        s_att0[m] = e0 * inv; s_att1[m] = e1 * inv;
      }
    }
    __syncthreads();
    if (threadIdx.x == 0) {
      bool used[MM];
#pragma unroll
      for (int j = 0; j < MM; j++) used[j] = false;
      for (int k = 0; k < KACT; k++) {
        int best = 0; float bvv = 3.402823466e38f;
        for (int j = 0; j < MM; j++)
          if (!used[j] && s_att0[j] < bvv) { bvv = s_att0[j]; best = j; }
        used[best] = true; s_act[k] = best;
        if (blockIdx.x == 0 && outTotal >= TT * MM * HH + TT * KACT)
          out[(size_t)TT * MM * HH + (size_t)t * KACT + k] = (float)best;
      }
      for (int j = 0; j < MM; j++) s_slot[j] = -1;
      for (int k = 0; k < KACT; k++) s_slot[s_act[k]] = k;
      int ii = 0;
      for (int j = 0; j < MM; j++) if (s_slot[j] < 0) s_inact[ii++] = j;
    }
    __syncthreads();
    {
      const int NH = (MM - KACT) * 2 * 4 * NCH;   // 1536 chunked tgemv tasks
      for (int task = gw; task < NH + KACT * DD; task += GWARPS) {
        if (task < NH) {
          int im = task % (MM - KACT);
          int r2 = task / (MM - KACT);            // 0..127
          int mat = r2 >> 6, qt = (r2 >> 4) & 3, ch = r2 & 15;
          int m = s_inact[im];
          const float* W = (mat ? Wvg : Wkg) + (size_t)m * HH * HH;
          tgemv_part(W, g_h + m * HH, g_part[mat + 1][m][ch], qt, ch, lane);
        } else {
          int lt = task - NH;
          int a = lt >> 9, r = lt & 511;
          int m = s_act[a];
          const float* xm = inputs + ((size_t)m * TT + t) * DD;
          float bvv = __ldg(bv + m * DD + r);
          float v1 = wdot<4, false, false>(Wv + (size_t)(m * DD + r) * DD, xm, lane) + bvv;
          if (lane == 0)
            g_sel[m * DD + r] = s_att0[m] * bvv + s_att1[m] * v1;
        }
      }
    }
    gbar(lgen);

    // ---- P3: LSTM gates for active (fused s1+s2, 2048 tasks); zero c for inactive ----
    for (int task = gw; task < KACT * HH; task += GWARPS) {
      int a = task >> 9, j = task & 511;
      int m = s_act[a];
      const float4* selp = (const float4*)(g_sel + m * DD);
      const float4* hp   = (const float4*)(g_h + m * HH);
      float4 sb[4], hb[4];
#pragma unroll
      for (int k = 0; k < 4; k++) {
        sb[k] = __ldcg(selp + lane + 32 * k);
        hb[k] = __ldcg(hp + lane + 32 * k);
      }
      const float* Wi = W_ih + (size_t)m * 4 * HH * DD;
      const float* Wh = W_hh + (size_t)m * 4 * HH * HH;
      float gv[4];
#pragma unroll
      for (int gq = 0; gq < 4; gq++) {
        int row = gq * HH + j;
        const float4* wi4 = (const float4*)(Wi + (size_t)row * DD);
        const float4* wh4 = (const float4*)(Wh + (size_t)row * HH);
        float s = 0.f;
#pragma unroll
        for (int k = 0; k < 4; k++) {
          float4 wa = __ldg(wi4 + lane + 32 * k);
          float4 wb = __ldg(wh4 + lane + 32 * k);
          s = fmaf(wa.x, sb[k].x, s); s = fmaf(wa.y, sb[k].y, s);
          s = fmaf(wa.z, sb[k].z, s); s = fmaf(wa.w, sb[k].w, s);
          s = fmaf(wb.x, hb[k].x, s); s = fmaf(wb.y, hb[k].y, s);
          s = fmaf(wb.z, hb[k].z, s); s = fmaf(wb.w, hb[k].w, s);
        }
        s = warp_reduce(s);
        if (lane == 0)
          gv[gq] = s + __ldg(b_ih + m * 4 * HH + row) + __ldg(b_hh + m * 4 * HH + row);
      }
      if (lane == 0) {
        float co = __ldcg(&g_c[m * HH + j]);
        float cn = sigf(gv[1]) * co + sigf(gv[0]) * tanhf(gv[2]);
        float hn = sigf(gv[3]) * tanhf(cn);
        __stcg(&g_c[m * HH + j], cn);
        __stcg(&g_th[m * HH + j], hn);
      }
    }
    for (int e = gt; e < (MM - KACT) * HH; e += NTHREADS) {
      int m = s_inact[e >> 9];
      __stcg(&g_c[m * HH + (e & 511)], 0.f);
    }
    gbar(lgen);

    // ---- P4: active q2/k2/v2 partials from temp_h (768 tasks) + inactive k2/v2 reduce ----
    for (int e = gt; e < (MM - KACT) * 2 * (HH / 4); e += NTHREADS) {   // 3072 float4 outputs
      int im = e >> 8;
      int rem = e & 255;
      int mat = rem >> 7, f4 = rem & 127;
      int m = s_inact[im];
      float4 acc = make_float4(0.f, 0.f, 0.f, 0.f);
#pragma unroll
      for (int ch = 0; ch < NCH; ch++) {
        float4 p = __ldcg((const float4*)g_part[mat + 1][m][ch] + f4);
        acc.x += p.x; acc.y += p.y; acc.z += p.z; acc.w += p.w;
      }
      float* dst = (mat ? g_v2 : g_k2) + m * HH;
      __stcg((float4*)dst + f4, acc);
    }
    for (int task = gw; task < 3 * KACT * 4 * NCH; task += GWARPS) {    // 768 tasks
      int mat = task >> 8;
      int rem = task & 255;
      int a = rem >> 6, qt = (rem >> 4) & 3, ch = rem & 15;
      int m = s_act[a];
      const float* W = (mat == 0 ? Wqg : (mat == 1 ? Wkg : Wvg)) + (size_t)m * HH * HH;
      tgemv_part(W, g_th + m * HH, g_part[mat][m][ch], qt, ch, lane);
    }
    gbar(lgen);

    // ---- P5a: reduce active q2/k2/v2 partials ----
    for (int e = gt; e < 3 * KACT * (HH / 4); e += NTHREADS) {          // 1536 float4 outputs
      int mat = e / (KACT * 128);
      int rem = e % (KACT * 128);
      int a = rem >> 7, f4 = rem & 127;
      int m = s_act[a];
      float4 acc = make_float4(0.f, 0.f, 0.f, 0.f);
#pragma unroll
      for (int ch = 0; ch < NCH; ch++) {
        float4 p = __ldcg((const float4*)g_part[mat][m][ch] + f4);
        acc.x += p.x; acc.y += p.y; acc.z += p.z; acc.w += p.w;
      }
      float* dst = (mat == 0 ? g_q2 : (mat == 1 ? g_k2 : g_v2)) + m * HH;
      __stcg((float4*)dst + f4, acc);
    }
    gbar(lgen);

    // ---- P5b: att2 logits (redundant per CTA), softmax, new_h, output ----
    for (int idx = threadIdx.x; idx < KACT * HH; idx += TPB)
      s_q2b[idx] = __ldcg(&g_q2[s_act[idx >> 9] * HH + (idx & 511)]);
    for (int idx = threadIdx.x; idx < MM * HH; idx += TPB)
      s_k2b[idx] = __ldcg(&g_k2[idx]);
    __syncthreads();
    for (int d6 = warp; d6 < KACT * MM; d6 += NWARP) {
      int a = d6 >> 4, j = d6 & 15;
      float s = sdot512(s_q2b + a * HH, s_k2b + j * HH, lane);
      if (lane == 0) s_s[d6] = s;
    }
    __syncthreads();
    if (threadIdx.x < KACT) {
      int a = threadIdx.x;
      float mx = -3.402823466e38f;
#pragma unroll
      for (int j = 0; j < MM; j++) mx = fmaxf(mx, s_s[a * MM + j]);
      float ev[MM]; float sum = 0.f;
#pragma unroll
      for (int j = 0; j < MM; j++) { ev[j] = expf(s_s[a * MM + j] - mx); sum += ev[j]; }
      float inv = 1.f / sum;
#pragma unroll
      for (int j = 0; j < MM; j++) s_w[a * MM + j] = ev[j] * inv;
    }
    __syncthreads();
    for (int e = gt; e < MM * (HH / 4); e += NTHREADS) {   // 2048 float4 outputs
      int m = e >> 7, f4 = e & 127;
      int a = s_slot[m];
      float4 val;
      if (a >= 0) {
        float4 acc = make_float4(0.f, 0.f, 0.f, 0.f);
#pragma unroll
        for (int j = 0; j < MM; j++) {
          float w = s_w[a * MM + j];
          float4 v = __ldcg((const float4*)(g_v2 + j * HH) + f4);
          acc.x = fmaf(w, v.x, acc.x); acc.y = fmaf(w, v.y, acc.y);
          acc.z = fmaf(w, v.z, acc.z); acc.w = fmaf(w, v.w, acc.w);
        }
        float4 th = __ldcg((const float4*)(g_th + m * HH) + f4);
        val.x = acc.x + th.x; val.y = acc.y + th.y;
        val.z = acc.z + th.z; val.w = acc.w + th.w;
        __stcg((float4*)(g_h + m * HH) + f4, val);
      } else {
        val = __ldcg((const float4*)g_h + e);
      }
      ((float4*)out)[(size_t)t * MM * (HH / 4) + e] = val;
    }
    gbar(lgen);
  }
}

// ---------------- launch ----------------
extern "C" void kernel_launch(void* const* d_in, const int* in_sizes, int n_in,
                              void* d_out, int out_size) {
  (void)in_sizes; (void)n_in;
  rim_kernel<<<NG, TPB>>>(
      (const float*)d_in[0],  (const float*)d_in[1],  (const float*)d_in[2],
      (const float*)d_in[3],  (const float*)d_in[4],  (const float*)d_in[5],
      (const float*)d_in[6],  (const float*)d_in[7],  (const float*)d_in[8],
      (const float*)d_in[9],  (const float*)d_in[10], (const float*)d_in[11],
      (const float*)d_in[12], (const float*)d_in[13],
      (float*)d_out, out_size);
}

// round 7
// speedup vs baseline: 3.5594x; 1.1824x over previous
#include <cuda_runtime.h>
#include <math.h>

#define MM    16
#define TT    512
#define DD    512
#define HH    512
#define QKN   256
#define KACT  4
#define NG    148
#define TPB   512
#define NWARP (TPB/32)              // 16
#define GWARPS (NG*NWARP)           // 2368
#define NTHREADS (NG*TPB)           // 75776
#define NCH   32                    // h-chunks per transposed GEMV
#define CHROWS (HH/NCH)             // 16
#define DYNSM 49152

// ---------------- persistent scratch (device globals; no allocs allowed) ----------------
__device__ __align__(16) float g_h  [MM*HH];
__device__ __align__(16) float g_c  [MM*HH];
__device__ __align__(16) float g_q  [MM*QKN];
__device__ __align__(16) float g_th [MM*HH];
__device__ __align__(16) float g_q2 [MM*HH];
__device__ __align__(16) float g_k2 [MM*HH];
__device__ __align__(16) float g_v2 [MM*HH];
__device__ __align__(16) float g_part[3][MM][NCH][HH];    // 0=q2,1=k2,2=v2 partials
__device__ __align__(16) float g_kxAll[(size_t)TT*MM*QKN]; // 8 MB: key_x + bk, all t
__device__ __align__(16) float g_v1All[(size_t)TT*MM*DD];  // 16 MB: val1 + bv, all t
__device__ unsigned g_barCnt;
__device__ unsigned g_barGen;

// ---------------- helpers ----------------
__device__ __forceinline__ float warp_reduce(float s) {
#pragma unroll
  for (int o = 16; o; o >>= 1) s += __shfl_xor_sync(0xffffffffu, s, o);
  return s;
}

__device__ __forceinline__ float sigf(float x) { return 1.f / (1.f + expf(-x)); }

template<int N4, bool ACG, bool BCG>
__device__ __forceinline__ float wdot(const float* __restrict__ A,
                                      const float* __restrict__ B, int lane) {
  const float4* a4 = (const float4*)A;
  const float4* b4 = (const float4*)B;
  float s = 0.f;
#pragma unroll
  for (int k = 0; k < N4; k++) {
    int idx = lane + 32 * k;
    float4 a = ACG ? __ldcg(a4 + idx) : __ldg(a4 + idx);
    float4 b = BCG ? __ldcg(b4 + idx) : __ldg(b4 + idx);
    s = fmaf(a.x, b.x, s); s = fmaf(a.y, b.y, s);
    s = fmaf(a.z, b.z, s); s = fmaf(a.w, b.w, s);
  }
  return warp_reduce(s);
}

// shared-memory dot of 512 floats
__device__ __forceinline__ float sdot512(const float* a, const float* b, int lane) {
  float s = 0.f;
#pragma unroll
  for (int k = 0; k < 4; k++) {
    float4 av = ((const float4*)a)[lane + 32 * k];
    float4 bv = ((const float4*)b)[lane + 32 * k];
    s = fmaf(av.x, bv.x, s); s = fmaf(av.y, bv.y, s);
    s = fmaf(av.z, bv.z, s); s = fmaf(av.w, bv.w, s);
  }
  return warp_reduce(s);
}

// Chunked transposed GEMV partial: out[o] = sum_{h in chunk} vec[h]*W[h*HH+o],
// o in [qt*128, qt*128+128). One warp.
__device__ __forceinline__ void tgemv_part(const float* __restrict__ W,
                                           const float* __restrict__ vec,
                                           float* __restrict__ outp,
                                           int qt, int ch, int lane) {
  const int o0 = qt * 128;
  const int h0 = ch * CHROWS;
  float4 acc = make_float4(0.f, 0.f, 0.f, 0.f);
  const float4* vp = (const float4*)(vec + h0);
#pragma unroll
  for (int i = 0; i < CHROWS / 4; i++) {            // 4 iterations
    float4 tv = __ldcg(vp + i);
    const float* base = W + (size_t)(h0 + i * 4) * HH + o0;
    float4 w0 = __ldg((const float4*)(base) + lane);
    float4 w1 = __ldg((const float4*)(base + HH) + lane);
    float4 w2 = __ldg((const float4*)(base + 2 * HH) + lane);
    float4 w3 = __ldg((const float4*)(base + 3 * HH) + lane);
    acc.x = fmaf(tv.x, w0.x, fmaf(tv.y, w1.x, fmaf(tv.z, w2.x, fmaf(tv.w, w3.x, acc.x))));
    acc.y = fmaf(tv.x, w0.y, fmaf(tv.y, w1.y, fmaf(tv.z, w2.y, fmaf(tv.w, w3.y, acc.y))));
    acc.z = fmaf(tv.x, w0.z, fmaf(tv.y, w1.z, fmaf(tv.z, w2.z, fmaf(tv.w, w3.z, acc.z))));
    acc.w = fmaf(tv.x, w0.w, fmaf(tv.y, w1.w, fmaf(tv.z, w2.w, fmaf(tv.w, w3.w, acc.w))));
  }
  __stcg((float4*)(outp + o0) + lane, acc);
}

// software grid barrier (all NG CTAs co-resident)
__device__ __forceinline__ void gbar(unsigned& lgen) {
  __syncthreads();
  if (threadIdx.x == 0) {
    __threadfence();
    if (atomicAdd(&g_barCnt, 1u) == (unsigned)(NG - 1)) {
      g_barCnt = 0u;
      __threadfence();
      atomicAdd(&g_barGen, 1u);
    } else {
      while (*((volatile unsigned*)&g_barGen) == lgen) { }
    }
    __threadfence();
  }
  lgen++;
  __syncthreads();
}

// ---------------- main persistent kernel ----------------
__global__ void __launch_bounds__(TPB, 1)
rim_kernel(const float* __restrict__ inputs,
           const float* __restrict__ Wq,  const float* __restrict__ bq,
           const float* __restrict__ Wk,  const float* __restrict__ bk,
           const float* __restrict__ Wv,  const float* __restrict__ bv,
           const float* __restrict__ W_ih, const float* __restrict__ b_ih,
           const float* __restrict__ W_hh, const float* __restrict__ b_hh,
           const float* __restrict__ Wqg, const float* __restrict__ Wkg,
           const float* __restrict__ Wvg,
           float* __restrict__ out, int outTotal) {
  const int lane = threadIdx.x & 31;
  const int warp = threadIdx.x >> 5;
  const int gw   = blockIdx.x * NWARP + warp;
  const int gt   = blockIdx.x * TPB + threadIdx.x;

  __shared__ float s_att0[MM], s_att1[MM], s_l0[MM];
  __shared__ int   s_act[KACT], s_slot[MM], s_dirty[MM], s_nDirty;
  __shared__ unsigned char s_isDirty[MM];
  __shared__ float s_s[KACT * MM], s_w[KACT * MM];
  extern __shared__ __align__(16) char dynsm[];
  float* s_k2b = (float*)dynsm;               // 32KB (phase E)
  float* s_q2b = (float*)(dynsm + 32768);     // 8KB  (phase E)
  float* s_sel = (float*)(dynsm + 40960);     // 8KB  (phase B)
  float (*sA)[32]   = (float(*)[32])dynsm;            // 8KB    (precompute)
  float (*sBT)[129] = (float(*)[129])(dynsm + 8192);  // 16.5KB (precompute)

  unsigned lgen = *((volatile unsigned*)&g_barGen);

  // ======== One-time precompute: kxAll = Wk@x_t+bk, v1All = Wv@x_t+bv (tiled GEMM) ========
  // Tile: 64 i-rows x 128 t-cols, K-chunks of 32. Thread computes 8i x 2t.
  {
    const int NKXT = MM * (QKN / 64) * (TT / 128);   // 256
    const int NTOT = NKXT + MM * (DD / 64) * (TT / 128); // 768
    const int ti = threadIdx.x >> 6;     // 0..7
    const int tt = threadIdx.x & 63;     // 0..63
    for (int tile = blockIdx.x; tile < NTOT; tile += NG) {
      int m, i0, t0, iN;
      const float* W; const float* bias; float* dst;
      if (tile < NKXT) {
        m = tile >> 4;                      // 16 tiles per m (4 iB x 4 tB)
        int r = tile & 15; i0 = (r >> 2) * 64; t0 = (r & 3) * 128;
        W = Wk + (size_t)m * QKN * DD; bias = bk + m * QKN; iN = QKN; dst = g_kxAll;
      } else {
        int tl = tile - NKXT;
        m = tl >> 5;                        // 32 tiles per m (8 iB x 4 tB)
        int r = tl & 31; i0 = (r >> 2) * 64; t0 = (r & 3) * 128;
        W = Wv + (size_t)m * DD * DD; bias = bv + m * DD; iN = DD; dst = g_v1All;
      }
      const float* X = inputs + (size_t)m * TT * DD;
      float acc0[8], acc1[8];
#pragma unroll
      for (int r8 = 0; r8 < 8; r8++) { acc0[r8] = 0.f; acc1[r8] = 0.f; }
      for (int kc = 0; kc < DD; kc += 32) {
        __syncthreads();
        { // load A: 64x32 floats, 1 float4/thread
          int ar = threadIdx.x >> 3, ac4 = threadIdx.x & 7;
          float4 v = __ldg((const float4*)(W + (size_t)(i0 + ar) * DD + kc) + ac4);
          *(float4*)&sA[ar][ac4 * 4] = v;
        }
        { // load X: 128x32 floats transposed into sBT, 2 float4/thread
#pragma unroll
          for (int j = 0; j < 2; j++) {
            int idx = threadIdx.x * 2 + j;
            int xr = idx >> 3, xc4 = idx & 7;
            float4 v = __ldg((const float4*)(X + (size_t)(t0 + xr) * DD + kc) + xc4);
            sBT[xc4 * 4 + 0][xr] = v.x; sBT[xc4 * 4 + 1][xr] = v.y;
            sBT[xc4 * 4 + 2][xr] = v.z; sBT[xc4 * 4 + 3][xr] = v.w;
          }
        }
        __syncthreads();
#pragma unroll
        for (int k = 0; k < 32; k++) {
          float b0 = sBT[k][tt], b1 = sBT[k][tt + 64];
#pragma unroll
          for (int r8 = 0; r8 < 8; r8++) {
            float a = sA[ti * 8 + r8][k];
            acc0[r8] = fmaf(a, b0, acc0[r8]);
            acc1[r8] = fmaf(a, b1, acc1[r8]);
          }
        }
      }
      __syncthreads();
#pragma unroll
      for (int j = 0; j < 2; j++) {
        int tcur = t0 + tt + j * 64;
        float* drow = dst + ((size_t)tcur * MM + m) * iN + i0 + ti * 8;
        float* ac = j ? acc1 : acc0;
#pragma unroll
        for (int r8 = 0; r8 < 8; r8++)
          drow[r8] = ac[r8] + __ldg(bias + i0 + ti * 8 + r8);
      }
    }
  }
  // init state + dirty set (t=0: everything dirty)
  for (int e = gt; e < MM * HH; e += NTHREADS) { g_h[e] = 0.f; g_c[e] = 0.f; }
  if (threadIdx.x == 0) {
    s_nDirty = MM;
    for (int j = 0; j < MM; j++) { s_dirty[j] = j; s_isDirty[j] = 1; }
  }
  gbar(lgen);

  const float scale = 1.f / 16.f;    // 1/sqrt(QK=256)

  for (int t = 0; t < TT; ++t) {
    const int nD = s_nDirty;

    // ==== Phase A: dirty-module q dots + dirty k2/v2 tgemv partials ====
    {
      const int nQ = nD * QKN;                 // full dot-512 tasks
      const int nT = nD * 2 * 4 * NCH;         // = nD*256 tgemv tasks
      for (int task = gw; task < nQ + nT; task += GWARPS) {
        if (task < nQ) {
          int di = task >> 8, i = task & 255;
          int m = s_dirty[di];
          float qv = wdot<4, false, true>(Wq + ((size_t)m * QKN + i) * HH, g_h + m * HH, lane);
          if (lane == 0) g_q[m * QKN + i] = qv + __ldg(bq + m * QKN + i);
        } else {
          int r = task - nQ;
          int di = r >> 8, r2 = r & 255;
          int mat = r2 >> 7, qt = (r2 >> 5) & 3, ch = r2 & 31;
          int m = s_dirty[di];
          const float* W = (mat ? Wvg : Wkg) + (size_t)m * HH * HH;
          tgemv_part(W, g_h + m * HH, g_part[mat + 1][m][ch], qt, ch, lane);
        }
      }
    }
    gbar(lgen);

    // ==== Phase B: logits/topk/sel (per-CTA) + dirty reduce + LSTM (distributed) ====
    if (warp < MM) {
      int m = warp;
      float l1 = wdot<2, true, false>(g_q + m * QKN,
                                      g_kxAll + ((size_t)t * MM + m) * QKN, lane);
      float l0 = 0.f;
      if (s_isDirty[m])
        l0 = wdot<2, true, false>(g_q + m * QKN, bk + m * QKN, lane);
      if (lane == 0) {
        if (s_isDirty[m]) s_l0[m] = l0 * scale;
        float L0 = s_l0[m], L1 = l1 * scale;
        float mx = fmaxf(L0, L1);
        float e0 = expf(L0 - mx), e1 = expf(L1 - mx);
        float inv = 1.f / (e0 + e1);
        s_att0[m] = e0 * inv; s_att1[m] = e1 * inv;
      }
    }
    __syncthreads();
    if (threadIdx.x == 0) {
      bool used[MM];
#pragma unroll
      for (int j = 0; j < MM; j++) used[j] = false;
      for (int k = 0; k < KACT; k++) {
        int best = 0; float bvv = 3.402823466e38f;
        for (int j = 0; j < MM; j++)
          if (!used[j] && s_att0[j] < bvv) { bvv = s_att0[j]; best = j; }
        used[best] = true; s_act[k] = best;
        if (blockIdx.x == 0 && outTotal >= TT * MM * HH + TT * KACT)
          out[(size_t)TT * MM * HH + (size_t)t * KACT + k] = (float)best;
      }
      for (int j = 0; j < MM; j++) s_slot[j] = -1;
      for (int k = 0; k < KACT; k++) s_slot[s_act[k]] = k;
    }
    __syncthreads();
    // sel into smem (per-CTA, from precomputed v1All)
    for (int idx = threadIdx.x; idx < KACT * DD; idx += TPB) {
      int a = idx >> 9, r = idx & 511;
      int m = s_act[a];
      float v1 = __ldg(&g_v1All[((size_t)t * MM + m) * DD + r]);
      s_sel[idx] = s_att0[m] * __ldg(bv + m * DD + r) + s_att1[m] * v1;
    }
    // reduce dirty k2/v2 partials (distributed globally; tiny)
    for (int e = gt; e < nD * 2 * 128; e += NTHREADS) {
      int di = e >> 8, rem = e & 255;
      int mat = rem >> 7, f4 = rem & 127;
      int m = s_dirty[di];
      float4 acc = make_float4(0.f, 0.f, 0.f, 0.f);
#pragma unroll 8
      for (int ch = 0; ch < NCH; ch++) {
        float4 p = __ldcg((const float4*)g_part[mat + 1][m][ch] + f4);
        acc.x += p.x; acc.y += p.y; acc.z += p.z; acc.w += p.w;
      }
      float* dst = (mat ? g_v2 : g_k2) + m * HH;
      __stcg((float4*)dst + f4, acc);
    }
    __syncthreads();     // s_sel ready for LSTM
    // LSTM gates for active modules (distributed warp tasks; sel from smem)
    for (int task = gw; task < KACT * HH; task += GWARPS) {
      int a = task >> 9, j = task & 511;
      int m = s_act[a];
      const float4* selp = (const float4*)(s_sel + a * DD);
      const float4* hp   = (const float4*)(g_h + m * HH);
      float4 sb[4], hb[4];
#pragma unroll
      for (int k = 0; k < 4; k++) {
        sb[k] = selp[lane + 32 * k];
        hb[k] = __ldcg(hp + lane + 32 * k);
      }
      const float* Wi = W_ih + (size_t)m * 4 * HH * DD;
      const float* Wh = W_hh + (size_t)m * 4 * HH * HH;
      float gv[4];
#pragma unroll
      for (int gq = 0; gq < 4; gq++) {
        int row = gq * HH + j;
        const float4* wi4 = (const float4*)(Wi + (size_t)row * DD);
        const float4* wh4 = (const float4*)(Wh + (size_t)row * HH);
        float s = 0.f;
#pragma unroll
        for (int k = 0; k < 4; k++) {
          float4 wa = __ldg(wi4 + lane + 32 * k);
          float4 wb = __ldg(wh4 + lane + 32 * k);
          s = fmaf(wa.x, sb[k].x, s); s = fmaf(wa.y, sb[k].y, s);
          s = fmaf(wa.z, sb[k].z, s); s = fmaf(wa.w, sb[k].w, s);
          s = fmaf(wb.x, hb[k].x, s); s = fmaf(wb.y, hb[k].y, s);
          s = fmaf(wb.z, hb[k].z, s); s = fmaf(wb.w, hb[k].w, s);
        }
        s = warp_reduce(s);
        if (lane == 0)
          gv[gq] = s + __ldg(b_ih + m * 4 * HH + row) + __ldg(b_hh + m * 4 * HH + row);
      }
      if (lane == 0) {
        float co = __ldcg(&g_c[m * HH + j]);
        float cn = sigf(gv[1]) * co + sigf(gv[0]) * tanhf(gv[2]);
        float hn = sigf(gv[3]) * tanhf(cn);
        __stcg(&g_c[m * HH + j], cn);
        __stcg(&g_th[m * HH + j], hn);
      }
    }
    // zero c for inactive (distributed)
    for (int e = gt; e < MM * HH; e += NTHREADS) {
      if (s_slot[e >> 9] < 0) __stcg(&g_c[e], 0.f);
    }
    __syncthreads();
    if (threadIdx.x == 0) {
      s_nDirty = KACT;
      for (int k = 0; k < KACT; k++) s_dirty[k] = s_act[k];
      for (int j = 0; j < MM; j++) s_isDirty[j] = (s_slot[j] >= 0) ? 1 : 0;
    }
    gbar(lgen);

    // ==== Phase C: active q2/k2/v2 tgemv partials from temp_h (1536 tasks) ====
    for (int task = gw; task < 3 * KACT * 4 * NCH; task += GWARPS) {
      int mat = task >> 9;
      int rem = task & 511;
      int a = rem >> 7, qt = (rem >> 5) & 3, ch = rem & 31;
      int m = s_act[a];
      const float* W = (mat == 0 ? Wqg : (mat == 1 ? Wkg : Wvg)) + (size_t)m * HH * HH;
      tgemv_part(W, g_th + m * HH, g_part[mat][m][ch], qt, ch, lane);
    }
    gbar(lgen);

    // ==== Phase D: reduce active partials -> g_q2/g_k2/g_v2 ====
    for (int e = gt; e < 3 * KACT * 128; e += NTHREADS) {
      int mat = e >> 9, rem = e & 511;
      int a = rem >> 7, f4 = rem & 127;
      int m = s_act[a];
      float4 acc = make_float4(0.f, 0.f, 0.f, 0.f);
#pragma unroll 8
      for (int ch = 0; ch < NCH; ch++) {
        float4 p = __ldcg((const float4*)g_part[mat][m][ch] + f4);
        acc.x += p.x; acc.y += p.y; acc.z += p.z; acc.w += p.w;
      }
      float* dst = (mat == 0 ? g_q2 : (mat == 1 ? g_k2 : g_v2)) + m * HH;
      __stcg((float4*)dst + f4, acc);
    }
    gbar(lgen);

    // ==== Phase E: att2 (per-CTA, smem), inter, new_h, output ====
    for (int idx = threadIdx.x; idx < KACT * HH; idx += TPB)
      s_q2b[idx] = __ldcg(&g_q2[s_act[idx >> 9] * HH + (idx & 511)]);
    for (int idx = threadIdx.x; idx < MM * HH; idx += TPB)
      s_k2b[idx] = __ldcg(&g_k2[idx]);
    __syncthreads();
    for (int d6 = warp; d6 < KACT * MM; d6 += NWARP) {
      int a = d6 >> 4, j = d6 & 15;
      float s = sdot512(s_q2b + a * HH, s_k2b + j * HH, lane);
      if (lane == 0) s_s[d6] = s;
    }
    __syncthreads();
    if (threadIdx.x < KACT) {
      int a = threadIdx.x;
      float mx = -3.402823466e38f;
#pragma unroll
      for (int j = 0; j < MM; j++) mx = fmaxf(mx, s_s[a * MM + j]);
      float ev[MM]; float sum = 0.f;
#pragma unroll
      for (int j = 0; j < MM; j++) { ev[j] = expf(s_s[a * MM + j] - mx); sum += ev[j]; }
      float inv = 1.f / sum;
#pragma unroll
      for (int j = 0; j < MM; j++) s_w[a * MM + j] = ev[j] * inv;
    }
    __syncthreads();
    for (int e = gt; e < MM * 128; e += NTHREADS) {
      int m = e >> 7, f4 = e & 127;
      int a = s_slot[m];
      float4 val;
      if (a >= 0) {
        float4 acc = make_float4(0.f, 0.f, 0.f, 0.f);
#pragma unroll
        for (int j = 0; j < MM; j++) {
          float w = s_w[a * MM + j];
          float4 v = __ldcg((const float4*)(g_v2 + j * HH) + f4);
          acc.x = fmaf(w, v.x, acc.x); acc.y = fmaf(w, v.y, acc.y);
          acc.z = fmaf(w, v.z, acc.z); acc.w = fmaf(w, v.w, acc.w);
        }
        float4 th = __ldcg((const float4*)(g_th + m * HH) + f4);
        val.x = acc.x + th.x; val.y = acc.y + th.y;
        val.z = acc.z + th.z; val.w = acc.w + th.w;
        __stcg((float4*)(g_h + m * HH) + f4, val);
      } else {
        val = __ldcg((const float4*)g_h + e);
      }
      ((float4*)out)[(size_t)t * MM * 128 + e] = val;
    }
    gbar(lgen);
  }
}

// ---------------- launch ----------------
extern "C" void kernel_launch(void* const* d_in, const int* in_sizes, int n_in,
                              void* d_out, int out_size) {
  (void)in_sizes; (void)n_in;
  cudaFuncSetAttribute(rim_kernel, cudaFuncAttributeMaxDynamicSharedMemorySize, DYNSM);
  rim_kernel<<<NG, TPB, DYNSM>>>(
      (const float*)d_in[0],  (const float*)d_in[1],  (const float*)d_in[2],
      (const float*)d_in[3],  (const float*)d_in[4],  (const float*)d_in[5],
      (const float*)d_in[6],  (const float*)d_in[7],  (const float*)d_in[8],
      (const float*)d_in[9],  (const float*)d_in[10], (const float*)d_in[11],
      (const float*)d_in[12], (const float*)d_in[13],
      (float*)d_out, out_size);
}